// round 1
// baseline (speedup 1.0000x reference)
#include <cuda_runtime.h>

// SPP: out = concat(x, pool5(x), pool9(x), pool13(x)) on channel axis.
// Uses pool9 = pool5(pool5(x)), pool13 = pool5(pool9) (stride-1, -inf pad SAME),
// and separable 1-D max passes in shared memory, one block per (n,c) plane.

#define NPLANES   8192      // 16 * 512
#define PLANE_F4  1024      // 64*64 / 4
#define THREADS   256

__device__ __forceinline__ float4 v4max(float4 a, float4 b) {
    return make_float4(fmaxf(a.x, b.x), fmaxf(a.y, b.y),
                       fmaxf(a.z, b.z), fmaxf(a.w, b.w));
}

__global__ __launch_bounds__(THREADS, 1)
void spp_kernel(const float4* __restrict__ in, float4* __restrict__ out) {
    __shared__ float4 A[PLANE_F4];  // current plane (64 rows x 16 float4)
    __shared__ float4 B[PLANE_F4];  // horizontal-pass temp

    const float NEG = __int_as_float(0xff800000);  // -inf
    const float4 NEG4 = make_float4(NEG, NEG, NEG, NEG);

    const int plane = blockIdx.x;           // n*512 + c
    const int n = plane >> 9;
    const int c = plane & 511;
    const int tid = threadIdx.x;

    const float4* src = in + (size_t)plane * PLANE_F4;
    // output sections: s=0 copy, s=1 pool5, s=2 pool9, s=3 pool13
    float4* out0 = out + ((size_t)n * 2048 + c) * PLANE_F4;

    // ---- load plane + write copy section ----
    #pragma unroll
    for (int i = 0; i < 4; i++) {
        int t = tid + i * THREADS;
        float4 v = src[t];
        A[t] = v;
        out0[t] = v;
    }
    __syncthreads();

    // ---- three cascaded pool5 stages ----
    #pragma unroll
    for (int pool = 0; pool < 3; pool++) {
        // horizontal pass: B[y][x] = max(A[y][x-2..x+2])
        #pragma unroll
        for (int i = 0; i < 4; i++) {
            int t = tid + i * THREADS;
            int g = t & 15;                  // float4 column group 0..15
            float4 cu = A[t];
            float4 p = (g > 0)  ? A[t - 1] : NEG4;
            float4 nx = (g < 15) ? A[t + 1] : NEG4;
            float m01 = fmaxf(cu.x, cu.y);
            float m23 = fmaxf(cu.z, cu.w);
            float m0123 = fmaxf(m01, m23);
            float4 o;
            o.x = fmaxf(fmaxf(p.z, p.w), fmaxf(m01, cu.z));
            o.y = fmaxf(p.w, m0123);
            o.z = fmaxf(m0123, nx.x);
            o.w = fmaxf(fmaxf(cu.y, m23), fmaxf(nx.x, nx.y));
            B[t] = o;
        }
        __syncthreads();

        // vertical pass: o = max(B[y-2..y+2][x]); write gmem section, feed A
        float4* outs = out0 + (size_t)(pool + 1) * 512 * PLANE_F4;
        #pragma unroll
        for (int i = 0; i < 4; i++) {
            int t = tid + i * THREADS;
            int y = t >> 4;
            float4 r0 = (y >= 2)  ? B[t - 32] : NEG4;
            float4 r1 = (y >= 1)  ? B[t - 16] : NEG4;
            float4 r2 = B[t];
            float4 r3 = (y <= 62) ? B[t + 16] : NEG4;
            float4 r4 = (y <= 61) ? B[t + 32] : NEG4;
            float4 o = v4max(v4max(v4max(r0, r1), v4max(r2, r3)), r4);
            if (pool < 2) A[t] = o;
            outs[t] = o;
        }
        if (pool < 2) __syncthreads();
    }
}

extern "C" void kernel_launch(void* const* d_in, const int* in_sizes, int n_in,
                              void* d_out, int out_size) {
    const float4* x = (const float4*)d_in[0];
    float4* out = (float4*)d_out;
    spp_kernel<<<NPLANES, THREADS>>>(x, out);
}

// round 2
// speedup vs baseline: 1.4742x; 1.4742x over previous
#include <cuda_runtime.h>

// SPP: out = concat(x, pool5(x), pool9(x), pool13(x)) along channels.
// pool9 = pool5(pool5(x)), pool13 = pool5(pool9); separable 1-D passes.
// R2: register-resident 4-row column strips per thread -> halve LDS/STS traffic.

#define NPLANES   8192      // 16 * 512
#define PLANE_F4  1024      // 64*64 / 4 (64 rows x 16 float4)
#define THREADS   256

__device__ __forceinline__ float4 v4max(float4 a, float4 b) {
    return make_float4(fmaxf(a.x, b.x), fmaxf(a.y, b.y),
                       fmaxf(a.z, b.z), fmaxf(a.w, b.w));
}

// 5-wide horizontal max over [p.z p.w | c.x c.y c.z c.w | n.x n.y]
__device__ __forceinline__ float4 hmax5(float4 p, float4 c, float4 n) {
    float m01 = fmaxf(c.x, c.y);
    float m23 = fmaxf(c.z, c.w);
    float m0123 = fmaxf(m01, m23);
    float4 o;
    o.x = fmaxf(fmaxf(p.z, p.w), fmaxf(m01, c.z));
    o.y = fmaxf(p.w, m0123);
    o.z = fmaxf(m0123, n.x);
    o.w = fmaxf(fmaxf(c.y, m23), fmaxf(n.x, n.y));
    return o;
}

__global__ __launch_bounds__(THREADS, 3)
void spp_kernel(const float4* __restrict__ in, float4* __restrict__ out) {
    __shared__ float4 A[PLANE_F4];  // v-pass results (neighbor-column exchange)
    __shared__ float4 B[PLANE_F4];  // h-pass results (neighbor-row exchange)

    const float NEG = __int_as_float(0xff800000);  // -inf
    const float4 NEG4 = make_float4(NEG, NEG, NEG, NEG);

    const int plane = blockIdx.x;           // n*512 + c
    const int n = plane >> 9;
    const int c = plane & 511;
    const int xg = threadIdx.x & 15;        // float4 column 0..15
    const int yg = threadIdx.x >> 4;        // row-strip 0..15 (rows 4*yg..4*yg+3)
    const int base = ((yg << 2) << 4) + xg; // index of row 4*yg, column xg

    const float4* src = in + (size_t)plane * PLANE_F4;
    float4* out0 = out + ((size_t)n * 2048 + c) * PLANE_F4;

    // ---- load strip + write copy section ----
    float4 v[4];
    #pragma unroll
    for (int r = 0; r < 4; r++) {
        int t = base + (r << 4);
        v[r] = src[t];
        A[t] = v[r];
        out0[t] = v[r];
    }
    __syncthreads();

    // ---- three cascaded pool5 stages ----
    #pragma unroll
    for (int pool = 0; pool < 3; pool++) {
        // horizontal pass: center from regs, neighbor columns from A
        float4 h[4];
        #pragma unroll
        for (int r = 0; r < 4; r++) {
            int t = base + (r << 4);
            float4 p  = (xg > 0)  ? A[t - 1] : NEG4;
            float4 nx = (xg < 15) ? A[t + 1] : NEG4;
            h[r] = hmax5(p, v[r], nx);
            B[t] = h[r];
        }
        __syncthreads();

        // vertical pass: my 4 h-rows in regs + 2 above + 2 below from B
        float4 u0 = (yg > 0)  ? B[base - 32] : NEG4;   // row 4yg-2
        float4 u1 = (yg > 0)  ? B[base - 16] : NEG4;   // row 4yg-1
        float4 d0 = (yg < 15) ? B[base + 64] : NEG4;   // row 4yg+4
        float4 d1 = (yg < 15) ? B[base + 80] : NEG4;   // row 4yg+5

        float4 m12  = v4max(h[1], h[2]);               // shared subexpression
        v[0] = v4max(v4max(u0, u1), v4max(h[0], m12));
        v[1] = v4max(v4max(u1, h[0]), v4max(m12, h[3]));
        v[2] = v4max(v4max(h[0], m12), v4max(h[3], d0));
        v[3] = v4max(v4max(m12, h[3]), v4max(d0, d1));

        float4* outs = out0 + (size_t)(pool + 1) * 512 * PLANE_F4;
        #pragma unroll
        for (int r = 0; r < 4; r++) {
            int t = base + (r << 4);
            if (pool < 2) A[t] = v[r];
            outs[t] = v[r];
        }
        if (pool < 2) __syncthreads();
    }
}

extern "C" void kernel_launch(void* const* d_in, const int* in_sizes, int n_in,
                              void* d_out, int out_size) {
    const float4* x = (const float4*)d_in[0];
    float4* out = (float4*)d_out;
    spp_kernel<<<NPLANES, THREADS>>>(x, out);
}